// round 4
// baseline (speedup 1.0000x reference)
#include <cuda_runtime.h>

#define Nn 10000
#define Ee 160000
#define Cc 8
#define Bb 64
#define EPSv 1e-5f

// Scratch (device globals; allocation-free per harness rules)
__device__ float g_xT[Ee * Bb];        // x transposed (E,B)
__device__ float g_h[Nn * Bb * Cc];    // LN+ELU activations, layout (N, B, C)
__device__ int   g_cnt[Nn];
__device__ int   g_cursor[Nn];
__device__ int   g_start[Nn + 1];
__device__ int   g_sorted[Ee];

// ---------------- hist + transpose fused (role-split grid) ----------------

#define HIST_BLOCKS 625           // 625*256 = 160000
#define TR_BLOCKS_X 5000          // Ee/32
#define TR_BLOCKS_Y 2             // Bb/32

__global__ void hist_transpose_kernel(const int* __restrict__ dst,
                                      const float* __restrict__ x) {
    int bid = blockIdx.x;
    if (bid < HIST_BLOCKS) {
        int e = bid * 256 + threadIdx.x;
        if (e < Ee) atomicAdd(&g_cnt[dst[e]], 1);
        return;
    }
    int tb = bid - HIST_BLOCKS;
    int e0 = (tb % TR_BLOCKS_X) * 32;
    int b0 = (tb / TR_BLOCKS_X) * 32;
    int tx = threadIdx.x & 31;
    int ty = threadIdx.x >> 5;    // 0..7
    __shared__ float tile[32][33];
#pragma unroll
    for (int i = 0; i < 32; i += 8)
        tile[ty + i][tx] = x[(b0 + ty + i) * Ee + e0 + tx];
    __syncthreads();
#pragma unroll
    for (int i = 0; i < 32; i += 8)
        g_xT[(e0 + ty + i) * Bb + b0 + tx] = tile[tx][ty + i];
}

// Single-block exclusive scan over N=10000 counts; also seeds g_cursor = g_start
__global__ void scan_kernel() {
    __shared__ int sh[1024];
    const int CH = (Nn + 1023) / 1024;  // 10
    int t = threadIdx.x;
    int base = t * CH;
    int loc[CH];
    int s = 0;
#pragma unroll
    for (int i = 0; i < CH; i++) {
        int v = (base + i < Nn) ? g_cnt[base + i] : 0;
        loc[i] = s;
        s += v;
    }
    sh[t] = s;
    __syncthreads();
    for (int off = 1; off < 1024; off <<= 1) {
        int v = (t >= off) ? sh[t - off] : 0;
        __syncthreads();
        if (t >= off) sh[t] += v;
        __syncthreads();
    }
    int prev = (t > 0) ? sh[t - 1] : 0;
#pragma unroll
    for (int i = 0; i < CH; i++)
        if (base + i < Nn) {
            int v = prev + loc[i];
            g_start[base + i] = v;
            g_cursor[base + i] = v;
        }
    if (t == 1023) g_start[Nn] = sh[1023];
}

__global__ void sort_scatter_kernel(const int* __restrict__ dst) {
    int e = blockIdx.x * blockDim.x + threadIdx.x;
    if (e < Ee) {
        int d = dst[e];
        int p = atomicAdd(&g_cursor[d], 1);
        g_sorted[p] = e;
    }
}

// ---------------- Fused scatter + bias + LayerNorm + ELU ----------------
// 64 threads per node (one per batch b); C=8 accumulators in registers.
// 4-edge unrolled mainloop with edge-id prefetch: MLP=4 on the xv load path.

__global__ void scatter_ln_kernel(const float* __restrict__ w1,
                                  const float* __restrict__ b1,
                                  const float* __restrict__ gamma,
                                  const float* __restrict__ beta) {
    int node = blockIdx.x * 4 + (threadIdx.x >> 6);
    int b    = threadIdx.x & 63;
    if (node >= Nn) return;

    // Hoist per-node parameter loads: issue early, consumed after the loop
    float4 c0 = *reinterpret_cast<const float4*>(b1 + node * 8);
    float4 c1 = *reinterpret_cast<const float4*>(b1 + node * 8 + 4);
    float4 ga = *reinterpret_cast<const float4*>(gamma + node * 8);
    float4 gb = *reinterpret_cast<const float4*>(gamma + node * 8 + 4);
    float4 ba = *reinterpret_cast<const float4*>(beta  + node * 8);
    float4 bb = *reinterpret_cast<const float4*>(beta  + node * 8 + 4);

    float acc[8];
#pragma unroll
    for (int j = 0; j < 8; j++) acc[j] = 0.0f;

    int s  = g_start[node];
    int se = g_start[node + 1];
    int n4 = (se - s) & ~3;       // edges handled by the unrolled loop
    int i  = s;

    if (n4 > 0) {
        // preload first chunk of 4 edge ids
        int e0 = g_sorted[i];
        int e1 = g_sorted[i + 1];
        int e2 = g_sorted[i + 2];
        int e3 = g_sorted[i + 3];
        for (; i < s + n4; i += 4) {
            // prefetch next chunk ids (overlaps with this chunk's loads/FMAs)
            int f0 = 0, f1 = 0, f2 = 0, f3 = 0;
            if (i + 4 < s + n4) {
                f0 = g_sorted[i + 4];
                f1 = g_sorted[i + 5];
                f2 = g_sorted[i + 6];
                f3 = g_sorted[i + 7];
            }
            // 4 independent xv loads (each 256B coalesced per 64-group)
            float xv0 = g_xT[e0 * Bb + b];
            float xv1 = g_xT[e1 * Bb + b];
            float xv2 = g_xT[e2 * Bb + b];
            float xv3 = g_xT[e3 * Bb + b];
            // 8 independent w1 float4 loads (broadcast within group)
            float4 wa0 = *reinterpret_cast<const float4*>(w1 + e0 * 8);
            float4 wb0 = *reinterpret_cast<const float4*>(w1 + e0 * 8 + 4);
            float4 wa1 = *reinterpret_cast<const float4*>(w1 + e1 * 8);
            float4 wb1 = *reinterpret_cast<const float4*>(w1 + e1 * 8 + 4);
            float4 wa2 = *reinterpret_cast<const float4*>(w1 + e2 * 8);
            float4 wb2 = *reinterpret_cast<const float4*>(w1 + e2 * 8 + 4);
            float4 wa3 = *reinterpret_cast<const float4*>(w1 + e3 * 8);
            float4 wb3 = *reinterpret_cast<const float4*>(w1 + e3 * 8 + 4);

            acc[0] = fmaf(xv0, wa0.x, acc[0]);
            acc[1] = fmaf(xv0, wa0.y, acc[1]);
            acc[2] = fmaf(xv0, wa0.z, acc[2]);
            acc[3] = fmaf(xv0, wa0.w, acc[3]);
            acc[4] = fmaf(xv0, wb0.x, acc[4]);
            acc[5] = fmaf(xv0, wb0.y, acc[5]);
            acc[6] = fmaf(xv0, wb0.z, acc[6]);
            acc[7] = fmaf(xv0, wb0.w, acc[7]);

            acc[0] = fmaf(xv1, wa1.x, acc[0]);
            acc[1] = fmaf(xv1, wa1.y, acc[1]);
            acc[2] = fmaf(xv1, wa1.z, acc[2]);
            acc[3] = fmaf(xv1, wa1.w, acc[3]);
            acc[4] = fmaf(xv1, wb1.x, acc[4]);
            acc[5] = fmaf(xv1, wb1.y, acc[5]);
            acc[6] = fmaf(xv1, wb1.z, acc[6]);
            acc[7] = fmaf(xv1, wb1.w, acc[7]);

            acc[0] = fmaf(xv2, wa2.x, acc[0]);
            acc[1] = fmaf(xv2, wa2.y, acc[1]);
            acc[2] = fmaf(xv2, wa2.z, acc[2]);
            acc[3] = fmaf(xv2, wa2.w, acc[3]);
            acc[4] = fmaf(xv2, wb2.x, acc[4]);
            acc[5] = fmaf(xv2, wb2.y, acc[5]);
            acc[6] = fmaf(xv2, wb2.z, acc[6]);
            acc[7] = fmaf(xv2, wb2.w, acc[7]);

            acc[0] = fmaf(xv3, wa3.x, acc[0]);
            acc[1] = fmaf(xv3, wa3.y, acc[1]);
            acc[2] = fmaf(xv3, wa3.z, acc[2]);
            acc[3] = fmaf(xv3, wa3.w, acc[3]);
            acc[4] = fmaf(xv3, wb3.x, acc[4]);
            acc[5] = fmaf(xv3, wb3.y, acc[5]);
            acc[6] = fmaf(xv3, wb3.z, acc[6]);
            acc[7] = fmaf(xv3, wb3.w, acc[7]);

            e0 = f0; e1 = f1; e2 = f2; e3 = f3;
        }
    }
    // tail (0..3 edges)
    for (; i < se; i++) {
        int e = g_sorted[i];
        float xv = g_xT[e * Bb + b];
        float4 wa = *reinterpret_cast<const float4*>(w1 + e * 8);
        float4 wb = *reinterpret_cast<const float4*>(w1 + e * 8 + 4);
        acc[0] = fmaf(xv, wa.x, acc[0]);
        acc[1] = fmaf(xv, wa.y, acc[1]);
        acc[2] = fmaf(xv, wa.z, acc[2]);
        acc[3] = fmaf(xv, wa.w, acc[3]);
        acc[4] = fmaf(xv, wb.x, acc[4]);
        acc[5] = fmaf(xv, wb.y, acc[5]);
        acc[6] = fmaf(xv, wb.z, acc[6]);
        acc[7] = fmaf(xv, wb.w, acc[7]);
    }

    acc[0] += c0.x; acc[1] += c0.y; acc[2] += c0.z; acc[3] += c0.w;
    acc[4] += c1.x; acc[5] += c1.y; acc[6] += c1.z; acc[7] += c1.w;

    float mu = 0.0f;
#pragma unroll
    for (int j = 0; j < 8; j++) mu += acc[j];
    mu *= 0.125f;
    float var = 0.0f;
#pragma unroll
    for (int j = 0; j < 8; j++) { float d = acc[j] - mu; var = fmaf(d, d, var); }
    var *= 0.125f;
    float r = rsqrtf(var + EPSv);

    float gv[8] = {ga.x, ga.y, ga.z, ga.w, gb.x, gb.y, gb.z, gb.w};
    float bv[8] = {ba.x, ba.y, ba.z, ba.w, bb.x, bb.y, bb.z, bb.w};

    float h[8];
#pragma unroll
    for (int j = 0; j < 8; j++) {
        float v = fmaf((acc[j] - mu) * r, gv[j], bv[j]);
        h[j] = (v > 0.0f) ? v : expm1f(v);        // ELU, alpha=1
    }

    float* hp = g_h + node * (Bb * Cc) + b * Cc;
    *reinterpret_cast<float4*>(hp)     = make_float4(h[0], h[1], h[2], h[3]);
    *reinterpret_cast<float4*>(hp + 4) = make_float4(h[4], h[5], h[6], h[7]);
}

// ---------------- Fused gather + transpose + residual via smem staging ----------------

#define GE 64  // edges per block

__global__ void gather_fused_kernel(const float* __restrict__ w3,
                                    const float* __restrict__ b3,
                                    const int* __restrict__ src,
                                    const float* __restrict__ x,
                                    float* __restrict__ out) {
    __shared__ float tile[Bb][GE + 1];
    int e0 = blockIdx.x * GE;
    int t = threadIdx.x;          // 256
    int b = t & 63;
    int g = t >> 6;               // 0..3

#pragma unroll 4
    for (int i = g; i < GE; i += 4) {
        int e = e0 + i;
        int sn = __ldg(src + e);                   // uniform within group
        const float* hp = g_h + sn * (Bb * Cc) + b * Cc;
        float4 ha = *reinterpret_cast<const float4*>(hp);
        float4 hb = *reinterpret_cast<const float4*>(hp + 4);
        float4 wa = *reinterpret_cast<const float4*>(w3 + e * 8);
        float4 wb = *reinterpret_cast<const float4*>(w3 + e * 8 + 4);
        float sum = __ldg(b3 + e);
        sum = fmaf(ha.x, wa.x, sum);
        sum = fmaf(ha.y, wa.y, sum);
        sum = fmaf(ha.z, wa.z, sum);
        sum = fmaf(ha.w, wa.w, sum);
        sum = fmaf(hb.x, wb.x, sum);
        sum = fmaf(hb.y, wb.y, sum);
        sum = fmaf(hb.z, wb.z, sum);
        sum = fmaf(hb.w, wb.w, sum);
        tile[b][i] = sum;                          // stride-65: conflict-free
    }
    __syncthreads();

    int el = t & 63;
#pragma unroll
    for (int k = 0; k < 16; k++) {
        int b2 = (t >> 6) + k * 4;
        int idx = b2 * Ee + e0 + el;
        out[idx] = tile[b2][el] + x[idx];
    }
}

// ---------------- Launch ----------------

extern "C" void kernel_launch(void* const* d_in, const int* in_sizes, int n_in,
                              void* d_out, int out_size) {
    const float* x     = (const float*)d_in[0];   // (B,E)
    const float* w1    = (const float*)d_in[1];   // (E,C)
    const float* b1    = (const float*)d_in[2];   // (N,C)
    const float* gamma = (const float*)d_in[3];   // (N,C)
    const float* beta  = (const float*)d_in[4];   // (N,C)
    const float* w3    = (const float*)d_in[5];   // (E,C)
    const float* b3    = (const float*)d_in[6];   // (E,)
    const int* edge_src = (const int*)d_in[7];    // (E,)
    const int* edge_dst = (const int*)d_in[8];    // (E,)
    float* out = (float*)d_out;                   // (B,E)

    // Zero histogram (memset node instead of kernel)
    void* cnt_ptr = nullptr;
    cudaGetSymbolAddress(&cnt_ptr, g_cnt);
    cudaMemsetAsync(cnt_ptr, 0, Nn * sizeof(int));

    // hist (atomics) overlapped with transpose (DRAM)
    hist_transpose_kernel<<<HIST_BLOCKS + TR_BLOCKS_X * TR_BLOCKS_Y, 256>>>(edge_dst, x);

    // scan (also seeds cursor), then counting-sort scatter
    scan_kernel<<<1, 1024>>>();
    sort_scatter_kernel<<<(Ee + 255) / 256, 256>>>(edge_dst);

    // Fused scatter + LN + ELU
    scatter_ln_kernel<<<(Nn + 3) / 4, 256>>>(w1, b1, gamma, beta);

    // Fused gather + transpose + residual
    gather_fused_kernel<<<Ee / GE, 256>>>(w3, b3, edge_src, x, out);
}

// round 5
// speedup vs baseline: 1.0501x; 1.0501x over previous
#include <cuda_runtime.h>

#define Nn 10000
#define Ee 160000
#define Cc 8
#define Bb 64
#define EPSv 1e-5f

// Scratch (device globals; allocation-free per harness rules)
__device__ float g_xT[Ee * Bb];        // x transposed AND permuted to CSR order: row i = edge g_sorted[i]
__device__ float g_w1s[Ee * Cc];       // w1 permuted to CSR order
__device__ float g_h[Nn * Bb * Cc];    // LN+ELU activations, layout (N, B, C)
__device__ int   g_cnt[Nn];
__device__ int   g_cursor[Nn];
__device__ int   g_start[Nn + 1];
__device__ int   g_rank[Ee];           // rank[e] = position of edge e in CSR order

// ---------------- histogram ----------------

__global__ void hist_kernel(const int* __restrict__ dst) {
    int e = blockIdx.x * blockDim.x + threadIdx.x;
    if (e < Ee) atomicAdd(&g_cnt[dst[e]], 1);
}

// Single-block exclusive scan over N=10000 counts; also seeds g_cursor = g_start
__global__ void scan_kernel() {
    __shared__ int sh[1024];
    const int CH = (Nn + 1023) / 1024;  // 10
    int t = threadIdx.x;
    int base = t * CH;
    int loc[CH];
    int s = 0;
#pragma unroll
    for (int i = 0; i < CH; i++) {
        int v = (base + i < Nn) ? g_cnt[base + i] : 0;
        loc[i] = s;
        s += v;
    }
    sh[t] = s;
    __syncthreads();
    for (int off = 1; off < 1024; off <<= 1) {
        int v = (t >= off) ? sh[t - off] : 0;
        __syncthreads();
        if (t >= off) sh[t] += v;
        __syncthreads();
    }
    int prev = (t > 0) ? sh[t - 1] : 0;
#pragma unroll
    for (int i = 0; i < CH; i++)
        if (base + i < Nn) {
            int v = prev + loc[i];
            g_start[base + i] = v;
            g_cursor[base + i] = v;
        }
    if (t == 1023) g_start[Nn] = sh[1023];
}

// Computes rank[e] and permutes w1 into CSR order in the same pass.
__global__ void sort_scatter_kernel(const int* __restrict__ dst,
                                    const float* __restrict__ w1) {
    int e = blockIdx.x * blockDim.x + threadIdx.x;
    if (e < Ee) {
        int d = dst[e];
        int p = atomicAdd(&g_cursor[d], 1);
        g_rank[e] = p;
        // copy w1 row (coalesced read: consecutive threads -> consecutive e)
        float4 wa = *reinterpret_cast<const float4*>(w1 + e * 8);
        float4 wb = *reinterpret_cast<const float4*>(w1 + e * 8 + 4);
        *reinterpret_cast<float4*>(g_w1s + p * 8)     = wa;
        *reinterpret_cast<float4*>(g_w1s + p * 8 + 4) = wb;
    }
}

// ---------------- Transpose x (B,E) -> permuted xT rows (CSR order) ----------------

__global__ void transpose_permute_kernel(const float* __restrict__ x) {
    __shared__ float tile[32][33];
    int e0 = blockIdx.x * 32;
    int b0 = blockIdx.y * 32;
    int tx = threadIdx.x, ty = threadIdx.y;  // block (32,8)
#pragma unroll
    for (int i = 0; i < 32; i += 8)
        tile[ty + i][tx] = x[(b0 + ty + i) * Ee + e0 + tx];
    __syncthreads();
#pragma unroll
    for (int i = 0; i < 32; i += 8) {
        int e = e0 + ty + i;
        int p = g_rank[e];                 // uniform per warp row -> broadcast load
        g_xT[p * Bb + b0 + tx] = tile[tx][ty + i];
    }
}

// ---------------- Fused scatter + bias + LayerNorm + ELU ----------------
// 64 threads per node; mainloop reads are PURE SEQUENTIAL (no indirection):
// addresses are induction variables -> full MLP without dependent-load chains.

__global__ void scatter_ln_kernel(const float* __restrict__ b1,
                                  const float* __restrict__ gamma,
                                  const float* __restrict__ beta) {
    int node = blockIdx.x * 4 + (threadIdx.x >> 6);
    int b    = threadIdx.x & 63;
    if (node >= Nn) return;

    float acc[8];
#pragma unroll
    for (int j = 0; j < 8; j++) acc[j] = 0.0f;

    int s  = g_start[node];
    int se = g_start[node + 1];
    int i  = s;

    // unroll-4: 4 independent xv loads issued up front; w loads sequential (L1/L2 friendly)
    for (; i + 4 <= se; i += 4) {
        float xv0 = g_xT[(i + 0) * Bb + b];
        float xv1 = g_xT[(i + 1) * Bb + b];
        float xv2 = g_xT[(i + 2) * Bb + b];
        float xv3 = g_xT[(i + 3) * Bb + b];

        float4 wa = *reinterpret_cast<const float4*>(g_w1s + (i + 0) * 8);
        float4 wb = *reinterpret_cast<const float4*>(g_w1s + (i + 0) * 8 + 4);
        acc[0] = fmaf(xv0, wa.x, acc[0]);
        acc[1] = fmaf(xv0, wa.y, acc[1]);
        acc[2] = fmaf(xv0, wa.z, acc[2]);
        acc[3] = fmaf(xv0, wa.w, acc[3]);
        acc[4] = fmaf(xv0, wb.x, acc[4]);
        acc[5] = fmaf(xv0, wb.y, acc[5]);
        acc[6] = fmaf(xv0, wb.z, acc[6]);
        acc[7] = fmaf(xv0, wb.w, acc[7]);

        wa = *reinterpret_cast<const float4*>(g_w1s + (i + 1) * 8);
        wb = *reinterpret_cast<const float4*>(g_w1s + (i + 1) * 8 + 4);
        acc[0] = fmaf(xv1, wa.x, acc[0]);
        acc[1] = fmaf(xv1, wa.y, acc[1]);
        acc[2] = fmaf(xv1, wa.z, acc[2]);
        acc[3] = fmaf(xv1, wa.w, acc[3]);
        acc[4] = fmaf(xv1, wb.x, acc[4]);
        acc[5] = fmaf(xv1, wb.y, acc[5]);
        acc[6] = fmaf(xv1, wb.z, acc[6]);
        acc[7] = fmaf(xv1, wb.w, acc[7]);

        wa = *reinterpret_cast<const float4*>(g_w1s + (i + 2) * 8);
        wb = *reinterpret_cast<const float4*>(g_w1s + (i + 2) * 8 + 4);
        acc[0] = fmaf(xv2, wa.x, acc[0]);
        acc[1] = fmaf(xv2, wa.y, acc[1]);
        acc[2] = fmaf(xv2, wa.z, acc[2]);
        acc[3] = fmaf(xv2, wa.w, acc[3]);
        acc[4] = fmaf(xv2, wb.x, acc[4]);
        acc[5] = fmaf(xv2, wb.y, acc[5]);
        acc[6] = fmaf(xv2, wb.z, acc[6]);
        acc[7] = fmaf(xv2, wb.w, acc[7]);

        wa = *reinterpret_cast<const float4*>(g_w1s + (i + 3) * 8);
        wb = *reinterpret_cast<const float4*>(g_w1s + (i + 3) * 8 + 4);
        acc[0] = fmaf(xv3, wa.x, acc[0]);
        acc[1] = fmaf(xv3, wa.y, acc[1]);
        acc[2] = fmaf(xv3, wa.z, acc[2]);
        acc[3] = fmaf(xv3, wa.w, acc[3]);
        acc[4] = fmaf(xv3, wb.x, acc[4]);
        acc[5] = fmaf(xv3, wb.y, acc[5]);
        acc[6] = fmaf(xv3, wb.z, acc[6]);
        acc[7] = fmaf(xv3, wb.w, acc[7]);
    }
    for (; i < se; i++) {
        float xv = g_xT[i * Bb + b];
        float4 wa = *reinterpret_cast<const float4*>(g_w1s + i * 8);
        float4 wb = *reinterpret_cast<const float4*>(g_w1s + i * 8 + 4);
        acc[0] = fmaf(xv, wa.x, acc[0]);
        acc[1] = fmaf(xv, wa.y, acc[1]);
        acc[2] = fmaf(xv, wa.z, acc[2]);
        acc[3] = fmaf(xv, wa.w, acc[3]);
        acc[4] = fmaf(xv, wb.x, acc[4]);
        acc[5] = fmaf(xv, wb.y, acc[5]);
        acc[6] = fmaf(xv, wb.z, acc[6]);
        acc[7] = fmaf(xv, wb.w, acc[7]);
    }

    float4 c0 = *reinterpret_cast<const float4*>(b1 + node * 8);
    float4 c1 = *reinterpret_cast<const float4*>(b1 + node * 8 + 4);
    acc[0] += c0.x; acc[1] += c0.y; acc[2] += c0.z; acc[3] += c0.w;
    acc[4] += c1.x; acc[5] += c1.y; acc[6] += c1.z; acc[7] += c1.w;

    float mu = 0.0f;
#pragma unroll
    for (int j = 0; j < 8; j++) mu += acc[j];
    mu *= 0.125f;
    float var = 0.0f;
#pragma unroll
    for (int j = 0; j < 8; j++) { float d = acc[j] - mu; var = fmaf(d, d, var); }
    var *= 0.125f;
    float r = rsqrtf(var + EPSv);

    float4 ga = *reinterpret_cast<const float4*>(gamma + node * 8);
    float4 gb = *reinterpret_cast<const float4*>(gamma + node * 8 + 4);
    float4 ba = *reinterpret_cast<const float4*>(beta  + node * 8);
    float4 bb = *reinterpret_cast<const float4*>(beta  + node * 8 + 4);

    float gv[8] = {ga.x, ga.y, ga.z, ga.w, gb.x, gb.y, gb.z, gb.w};
    float bv[8] = {ba.x, ba.y, ba.z, ba.w, bb.x, bb.y, bb.z, bb.w};

    float h[8];
#pragma unroll
    for (int j = 0; j < 8; j++) {
        float v = fmaf((acc[j] - mu) * r, gv[j], bv[j]);
        h[j] = (v > 0.0f) ? v : expm1f(v);        // ELU, alpha=1
    }

    float* hp = g_h + node * (Bb * Cc) + b * Cc;
    *reinterpret_cast<float4*>(hp)     = make_float4(h[0], h[1], h[2], h[3]);
    *reinterpret_cast<float4*>(hp + 4) = make_float4(h[4], h[5], h[6], h[7]);
}

// ---------------- Fused gather + transpose + residual via smem staging ----------------

#define GE 64  // edges per block

__global__ void gather_fused_kernel(const float* __restrict__ w3,
                                    const float* __restrict__ b3,
                                    const int* __restrict__ src,
                                    const float* __restrict__ x,
                                    float* __restrict__ out) {
    __shared__ float tile[Bb][GE + 1];
    int e0 = blockIdx.x * GE;
    int t = threadIdx.x;          // 256
    int b = t & 63;
    int g = t >> 6;               // 0..3

#pragma unroll 4
    for (int i = g; i < GE; i += 4) {
        int e = e0 + i;
        int sn = __ldg(src + e);                   // uniform within group
        const float* hp = g_h + sn * (Bb * Cc) + b * Cc;
        float4 ha = *reinterpret_cast<const float4*>(hp);
        float4 hb = *reinterpret_cast<const float4*>(hp + 4);
        float4 wa = *reinterpret_cast<const float4*>(w3 + e * 8);
        float4 wb = *reinterpret_cast<const float4*>(w3 + e * 8 + 4);
        float sum = __ldg(b3 + e);
        sum = fmaf(ha.x, wa.x, sum);
        sum = fmaf(ha.y, wa.y, sum);
        sum = fmaf(ha.z, wa.z, sum);
        sum = fmaf(ha.w, wa.w, sum);
        sum = fmaf(hb.x, wb.x, sum);
        sum = fmaf(hb.y, wb.y, sum);
        sum = fmaf(hb.z, wb.z, sum);
        sum = fmaf(hb.w, wb.w, sum);
        tile[b][i] = sum;                          // stride-65: conflict-free
    }
    __syncthreads();

    int el = t & 63;
#pragma unroll
    for (int k = 0; k < 16; k++) {
        int b2 = (t >> 6) + k * 4;
        int idx = b2 * Ee + e0 + el;
        out[idx] = tile[b2][el] + x[idx];
    }
}

// ---------------- Launch ----------------

extern "C" void kernel_launch(void* const* d_in, const int* in_sizes, int n_in,
                              void* d_out, int out_size) {
    const float* x     = (const float*)d_in[0];   // (B,E)
    const float* w1    = (const float*)d_in[1];   // (E,C)
    const float* b1    = (const float*)d_in[2];   // (N,C)
    const float* gamma = (const float*)d_in[3];   // (N,C)
    const float* beta  = (const float*)d_in[4];   // (N,C)
    const float* w3    = (const float*)d_in[5];   // (E,C)
    const float* b3    = (const float*)d_in[6];   // (E,)
    const int* edge_src = (const int*)d_in[7];    // (E,)
    const int* edge_dst = (const int*)d_in[8];    // (E,)
    float* out = (float*)d_out;                   // (B,E)

    // Zero histogram (memset node instead of kernel)
    void* cnt_ptr = nullptr;
    cudaGetSymbolAddress(&cnt_ptr, g_cnt);
    cudaMemsetAsync(cnt_ptr, 0, Nn * sizeof(int));

    hist_kernel<<<(Ee + 255) / 256, 256>>>(edge_dst);
    scan_kernel<<<1, 1024>>>();
    sort_scatter_kernel<<<(Ee + 255) / 256, 256>>>(edge_dst, w1);

    // Transpose x directly into CSR-permuted row order
    transpose_permute_kernel<<<dim3(Ee / 32, Bb / 32), dim3(32, 8)>>>(x);

    // Fused scatter + LN + ELU (pure streaming mainloop)
    scatter_ln_kernel<<<(Nn + 3) / 4, 256>>>(b1, gamma, beta);

    // Fused gather + transpose + residual
    gather_fused_kernel<<<Ee / GE, 256>>>(w3, b3, edge_src, x, out);
}

// round 6
// speedup vs baseline: 1.1504x; 1.0955x over previous
#include <cuda_runtime.h>

#define Nn 10000
#define Ee 160000
#define Cc 8
#define Bb 64
#define EPSv 1e-5f

// Scratch (device globals; allocation-free per harness rules)
__device__ float g_xT[Ee * Bb];        // x transposed AND permuted to CSR order
__device__ float g_w1s[Ee * Cc];       // w1 permuted to CSR order
__device__ float g_h[Nn * Bb * Cc];    // LN+ELU activations, layout (N, B, C)
__device__ int   g_cnt[Nn];
__device__ int   g_cursor[Nn];
__device__ int   g_start[Nn + 1];

// ---------------- histogram ----------------

__global__ void hist_kernel(const int* __restrict__ dst) {
    int e = blockIdx.x * blockDim.x + threadIdx.x;
    if (e < Ee) atomicAdd(&g_cnt[dst[e]], 1);
}

// Single-block exclusive scan over N=10000 counts; also seeds g_cursor = g_start
__global__ void scan_kernel() {
    __shared__ int sh[1024];
    const int CH = (Nn + 1023) / 1024;  // 10
    int t = threadIdx.x;
    int base = t * CH;
    int loc[CH];
    int s = 0;
#pragma unroll
    for (int i = 0; i < CH; i++) {
        int v = (base + i < Nn) ? g_cnt[base + i] : 0;
        loc[i] = s;
        s += v;
    }
    sh[t] = s;
    __syncthreads();
    for (int off = 1; off < 1024; off <<= 1) {
        int v = (t >= off) ? sh[t - off] : 0;
        __syncthreads();
        if (t >= off) sh[t] += v;
        __syncthreads();
    }
    int prev = (t > 0) ? sh[t - 1] : 0;
#pragma unroll
    for (int i = 0; i < CH; i++)
        if (base + i < Nn) {
            int v = prev + loc[i];
            g_start[base + i] = v;
            g_cursor[base + i] = v;
        }
    if (t == 1023) g_start[Nn] = sh[1023];
}

// ---------------- Fused rank-assign + transpose + permute (x and w1) ----------------
// Block owns 32 edge columns x all 64 b. Warp 0 computes CSR ranks via atomics
// (latency hidden under the 8KB x-tile load); then each permuted xT row is
// written as one contiguous 256B store, and w1 rows are permuted in-kernel.

__global__ void transpose_sort_kernel(const float* __restrict__ x,
                                      const int* __restrict__ dst,
                                      const float* __restrict__ w1) {
    __shared__ float tile[32][65];   // [e_local][b]
    __shared__ int ranks[32];
    int e0 = blockIdx.x * 32;
    int t = threadIdx.x;             // 256

    // warp 0: assign CSR ranks for these 32 edges
    if (t < 32) {
        int d = dst[e0 + t];
        ranks[t] = atomicAdd(&g_cursor[d], 1);
    }

    // all threads: load x tile (coalesced 128B rows), transposed into smem
    int tx = t & 31, ty = t >> 5;    // tx = e_local, ty = 0..7
#pragma unroll
    for (int i = 0; i < 64; i += 8)
        tile[tx][ty + i] = x[(ty + i) * Ee + e0 + tx];
    __syncthreads();

    // write permuted xT rows: 4 rows per iteration, 256B contiguous per row
    int b = t & 63, r = t >> 6;      // r = 0..3
#pragma unroll
    for (int i = 0; i < 32; i += 4)
        g_xT[ranks[r + i] * Bb + b] = tile[r + i][b];

    // permute w1: thread t handles element t of this block's 32x8 w1 chunk
    int er = t >> 3, c = t & 7;
    g_w1s[ranks[er] * 8 + c] = w1[e0 * 8 + t];
}

// ---------------- Fused scatter + bias + LayerNorm + ELU ----------------
// 64 threads per node; mainloop reads are PURE SEQUENTIAL (no indirection).

__global__ void scatter_ln_kernel(const float* __restrict__ b1,
                                  const float* __restrict__ gamma,
                                  const float* __restrict__ beta) {
    int node = blockIdx.x * 4 + (threadIdx.x >> 6);
    int b    = threadIdx.x & 63;
    if (node >= Nn) return;

    float acc[8];
#pragma unroll
    for (int j = 0; j < 8; j++) acc[j] = 0.0f;

    int s  = g_start[node];
    int se = g_start[node + 1];
    int i  = s;

    for (; i + 4 <= se; i += 4) {
        float xv0 = g_xT[(i + 0) * Bb + b];
        float xv1 = g_xT[(i + 1) * Bb + b];
        float xv2 = g_xT[(i + 2) * Bb + b];
        float xv3 = g_xT[(i + 3) * Bb + b];

        float4 wa = *reinterpret_cast<const float4*>(g_w1s + (i + 0) * 8);
        float4 wb = *reinterpret_cast<const float4*>(g_w1s + (i + 0) * 8 + 4);
        acc[0] = fmaf(xv0, wa.x, acc[0]);
        acc[1] = fmaf(xv0, wa.y, acc[1]);
        acc[2] = fmaf(xv0, wa.z, acc[2]);
        acc[3] = fmaf(xv0, wa.w, acc[3]);
        acc[4] = fmaf(xv0, wb.x, acc[4]);
        acc[5] = fmaf(xv0, wb.y, acc[5]);
        acc[6] = fmaf(xv0, wb.z, acc[6]);
        acc[7] = fmaf(xv0, wb.w, acc[7]);

        wa = *reinterpret_cast<const float4*>(g_w1s + (i + 1) * 8);
        wb = *reinterpret_cast<const float4*>(g_w1s + (i + 1) * 8 + 4);
        acc[0] = fmaf(xv1, wa.x, acc[0]);
        acc[1] = fmaf(xv1, wa.y, acc[1]);
        acc[2] = fmaf(xv1, wa.z, acc[2]);
        acc[3] = fmaf(xv1, wa.w, acc[3]);
        acc[4] = fmaf(xv1, wb.x, acc[4]);
        acc[5] = fmaf(xv1, wb.y, acc[5]);
        acc[6] = fmaf(xv1, wb.z, acc[6]);
        acc[7] = fmaf(xv1, wb.w, acc[7]);

        wa = *reinterpret_cast<const float4*>(g_w1s + (i + 2) * 8);
        wb = *reinterpret_cast<const float4*>(g_w1s + (i + 2) * 8 + 4);
        acc[0] = fmaf(xv2, wa.x, acc[0]);
        acc[1] = fmaf(xv2, wa.y, acc[1]);
        acc[2] = fmaf(xv2, wa.z, acc[2]);
        acc[3] = fmaf(xv2, wa.w, acc[3]);
        acc[4] = fmaf(xv2, wb.x, acc[4]);
        acc[5] = fmaf(xv2, wb.y, acc[5]);
        acc[6] = fmaf(xv2, wb.z, acc[6]);
        acc[7] = fmaf(xv2, wb.w, acc[7]);

        wa = *reinterpret_cast<const float4*>(g_w1s + (i + 3) * 8);
        wb = *reinterpret_cast<const float4*>(g_w1s + (i + 3) * 8 + 4);
        acc[0] = fmaf(xv3, wa.x, acc[0]);
        acc[1] = fmaf(xv3, wa.y, acc[1]);
        acc[2] = fmaf(xv3, wa.z, acc[2]);
        acc[3] = fmaf(xv3, wa.w, acc[3]);
        acc[4] = fmaf(xv3, wb.x, acc[4]);
        acc[5] = fmaf(xv3, wb.y, acc[5]);
        acc[6] = fmaf(xv3, wb.z, acc[6]);
        acc[7] = fmaf(xv3, wb.w, acc[7]);
    }
    for (; i < se; i++) {
        float xv = g_xT[i * Bb + b];
        float4 wa = *reinterpret_cast<const float4*>(g_w1s + i * 8);
        float4 wb = *reinterpret_cast<const float4*>(g_w1s + i * 8 + 4);
        acc[0] = fmaf(xv, wa.x, acc[0]);
        acc[1] = fmaf(xv, wa.y, acc[1]);
        acc[2] = fmaf(xv, wa.z, acc[2]);
        acc[3] = fmaf(xv, wa.w, acc[3]);
        acc[4] = fmaf(xv, wb.x, acc[4]);
        acc[5] = fmaf(xv, wb.y, acc[5]);
        acc[6] = fmaf(xv, wb.z, acc[6]);
        acc[7] = fmaf(xv, wb.w, acc[7]);
    }

    float4 c0 = *reinterpret_cast<const float4*>(b1 + node * 8);
    float4 c1 = *reinterpret_cast<const float4*>(b1 + node * 8 + 4);
    acc[0] += c0.x; acc[1] += c0.y; acc[2] += c0.z; acc[3] += c0.w;
    acc[4] += c1.x; acc[5] += c1.y; acc[6] += c1.z; acc[7] += c1.w;

    float mu = 0.0f;
#pragma unroll
    for (int j = 0; j < 8; j++) mu += acc[j];
    mu *= 0.125f;
    float var = 0.0f;
#pragma unroll
    for (int j = 0; j < 8; j++) { float d = acc[j] - mu; var = fmaf(d, d, var); }
    var *= 0.125f;
    float r = rsqrtf(var + EPSv);

    float4 ga = *reinterpret_cast<const float4*>(gamma + node * 8);
    float4 gb = *reinterpret_cast<const float4*>(gamma + node * 8 + 4);
    float4 ba = *reinterpret_cast<const float4*>(beta  + node * 8);
    float4 bb = *reinterpret_cast<const float4*>(beta  + node * 8 + 4);

    float gv[8] = {ga.x, ga.y, ga.z, ga.w, gb.x, gb.y, gb.z, gb.w};
    float bv[8] = {ba.x, ba.y, ba.z, ba.w, bb.x, bb.y, bb.z, bb.w};

    float h[8];
#pragma unroll
    for (int j = 0; j < 8; j++) {
        float v = fmaf((acc[j] - mu) * r, gv[j], bv[j]);
        h[j] = (v > 0.0f) ? v : expm1f(v);        // ELU, alpha=1
    }

    float* hp = g_h + node * (Bb * Cc) + b * Cc;
    *reinterpret_cast<float4*>(hp)     = make_float4(h[0], h[1], h[2], h[3]);
    *reinterpret_cast<float4*>(hp + 4) = make_float4(h[4], h[5], h[6], h[7]);
}

// ---------------- Fused gather + transpose + residual via smem staging ----------------

#define GE 64  // edges per block

__global__ void gather_fused_kernel(const float* __restrict__ w3,
                                    const float* __restrict__ b3,
                                    const int* __restrict__ src,
                                    const float* __restrict__ x,
                                    float* __restrict__ out) {
    __shared__ float tile[Bb][GE + 1];
    int e0 = blockIdx.x * GE;
    int t = threadIdx.x;          // 256
    int b = t & 63;
    int g = t >> 6;               // 0..3

#pragma unroll 4
    for (int i = g; i < GE; i += 4) {
        int e = e0 + i;
        int sn = __ldg(src + e);                   // uniform within group
        const float* hp = g_h + sn * (Bb * Cc) + b * Cc;
        float4 ha = *reinterpret_cast<const float4*>(hp);
        float4 hb = *reinterpret_cast<const float4*>(hp + 4);
        float4 wa = *reinterpret_cast<const float4*>(w3 + e * 8);
        float4 wb = *reinterpret_cast<const float4*>(w3 + e * 8 + 4);
        float sum = __ldg(b3 + e);
        sum = fmaf(ha.x, wa.x, sum);
        sum = fmaf(ha.y, wa.y, sum);
        sum = fmaf(ha.z, wa.z, sum);
        sum = fmaf(ha.w, wa.w, sum);
        sum = fmaf(hb.x, wb.x, sum);
        sum = fmaf(hb.y, wb.y, sum);
        sum = fmaf(hb.z, wb.z, sum);
        sum = fmaf(hb.w, wb.w, sum);
        tile[b][i] = sum;                          // stride-65: conflict-free
    }
    __syncthreads();

    int el = t & 63;
#pragma unroll
    for (int k = 0; k < 16; k++) {
        int b2 = (t >> 6) + k * 4;
        int idx = b2 * Ee + e0 + el;
        out[idx] = tile[b2][el] + x[idx];
    }
}

// ---------------- Launch ----------------

extern "C" void kernel_launch(void* const* d_in, const int* in_sizes, int n_in,
                              void* d_out, int out_size) {
    const float* x     = (const float*)d_in[0];   // (B,E)
    const float* w1    = (const float*)d_in[1];   // (E,C)
    const float* b1    = (const float*)d_in[2];   // (N,C)
    const float* gamma = (const float*)d_in[3];   // (N,C)
    const float* beta  = (const float*)d_in[4];   // (N,C)
    const float* w3    = (const float*)d_in[5];   // (E,C)
    const float* b3    = (const float*)d_in[6];   // (E,)
    const int* edge_src = (const int*)d_in[7];    // (E,)
    const int* edge_dst = (const int*)d_in[8];    // (E,)
    float* out = (float*)d_out;                   // (B,E)

    // Zero histogram
    void* cnt_ptr = nullptr;
    cudaGetSymbolAddress(&cnt_ptr, g_cnt);
    cudaMemsetAsync(cnt_ptr, 0, Nn * sizeof(int));

    hist_kernel<<<(Ee + 255) / 256, 256>>>(edge_dst);
    scan_kernel<<<1, 1024>>>();

    // Fused rank-assign + transpose + permute (replaces sort_scatter + transpose)
    transpose_sort_kernel<<<Ee / 32, 256>>>(x, edge_dst, w1);

    // Fused scatter + LN + ELU (pure streaming mainloop)
    scatter_ln_kernel<<<(Nn + 3) / 4, 256>>>(b1, gamma, beta);

    // Fused gather + transpose + residual
    gather_fused_kernel<<<Ee / GE, 256>>>(w3, b3, edge_src, x, out);
}